// round 1
// baseline (speedup 1.0000x reference)
#include <cuda_runtime.h>

#define N_NODES 100000
#define N_FEAT  128
#define N_EDGES 1600000

// Scratch: degree, D^{-1/2}, and the post-GEMM features (51.2 MB).
__device__ float g_deg[N_NODES];
__device__ float g_dinv[N_NODES];
__device__ float g_xw[(size_t)N_NODES * N_FEAT];

// ---------------------------------------------------------------------------
// 1) degree init: self-loop contributes 1 to every node
__global__ void k_deg_init() {
    int i = blockIdx.x * blockDim.x + threadIdx.x;
    if (i < N_NODES) g_deg[i] = 1.0f;
}

// 2) degree count over target nodes (col)
__global__ void k_deg_count(const int* __restrict__ col) {
    int e = blockIdx.x * blockDim.x + threadIdx.x;
    if (e < N_EDGES) atomicAdd(&g_deg[col[e]], 1.0f);
}

// 3) dinv = rsqrt(deg)  (deg >= 1 always, no zero branch needed)
__global__ void k_dinv() {
    int i = blockIdx.x * blockDim.x + threadIdx.x;
    if (i < N_NODES) g_dinv[i] = rsqrtf(g_deg[i]);
}

// ---------------------------------------------------------------------------
// 4) GEMM: xw = x @ W^T, fused epilogue writes the self-loop term + bias into
//    out, and stages xw for the edge scatter.
//    Block: 128 threads (one per output column), 8 rows per block.
__global__ void k_gemm(const float* __restrict__ x,
                       const float* __restrict__ W,
                       const float* __restrict__ b,
                       float* __restrict__ out) {
    __shared__ float4 xs[8][32];     // 8 rows x 128 floats of x
    const int j = threadIdx.x;       // output column 0..127
    const int row0 = blockIdx.x * 8;

    // cooperative load of the 8-row x tile (vectorized)
    const float4* xsrc = reinterpret_cast<const float4*>(x + (size_t)row0 * N_FEAT);
    #pragma unroll
    for (int idx = j; idx < 8 * 32; idx += 128) {
        xs[idx >> 5][idx & 31] = xsrc[idx];
    }
    __syncthreads();

    float acc[8] = {0.f, 0.f, 0.f, 0.f, 0.f, 0.f, 0.f, 0.f};
    const float4* Wv = reinterpret_cast<const float4*>(W + (size_t)j * N_FEAT);
    #pragma unroll
    for (int k4 = 0; k4 < 32; ++k4) {
        const float4 w = Wv[k4];                 // L1-hot: W is 64KB, reused by all blocks
        #pragma unroll
        for (int r = 0; r < 8; ++r) {
            const float4 xv = xs[r][k4];         // smem broadcast, conflict-free
            acc[r] += xv.x * w.x + xv.y * w.y + xv.z * w.z + xv.w * w.w;
        }
    }

    const float bj = b[j];
    #pragma unroll
    for (int r = 0; r < 8; ++r) {
        const int row = row0 + r;
        const float di = g_dinv[row];
        g_xw[(size_t)row * N_FEAT + j] = acc[r];
        // self-loop message (norm = dinv^2) + bias initializes out
        out[(size_t)row * N_FEAT + j] = acc[r] * di * di + bj;
    }
}

// ---------------------------------------------------------------------------
// 5) Edge scatter: one warp per edge. Gather xw[row] (float4/lane = 128 floats),
//    scale by dinv[row]*dinv[col], atomically accumulate into out[col].
__global__ void k_scatter(const int* __restrict__ ei,
                          float* __restrict__ out) {
    const int warp_id = (blockIdx.x * blockDim.x + threadIdx.x) >> 5;
    const int lane = threadIdx.x & 31;
    if (warp_id >= N_EDGES) return;

    const int r = ei[warp_id];             // source (row)
    const int c = ei[N_EDGES + warp_id];   // target (col)
    const float nrm = g_dinv[r] * g_dinv[c];

    const float4* src = reinterpret_cast<const float4*>(g_xw + (size_t)r * N_FEAT);
    float4 v = src[lane];
    v.x *= nrm; v.y *= nrm; v.z *= nrm; v.w *= nrm;

    float* dst = out + (size_t)c * N_FEAT + lane * 4;
    atomicAdd(dst + 0, v.x);
    atomicAdd(dst + 1, v.y);
    atomicAdd(dst + 2, v.z);
    atomicAdd(dst + 3, v.w);
}

// ---------------------------------------------------------------------------
extern "C" void kernel_launch(void* const* d_in, const int* in_sizes, int n_in,
                              void* d_out, int out_size) {
    const float* x  = (const float*)d_in[0];   // [100000, 128]
    const int*   ei = (const int*)  d_in[1];   // [2, 1600000]
    const float* W  = (const float*)d_in[2];   // [128, 128]
    const float* b  = (const float*)d_in[3];   // [128]
    float* out = (float*)d_out;                // [100000, 128]

    k_deg_init <<<(N_NODES + 255) / 256, 256>>>();
    k_deg_count<<<(N_EDGES + 255) / 256, 256>>>(ei + N_EDGES);
    k_dinv     <<<(N_NODES + 255) / 256, 256>>>();
    k_gemm     <<<N_NODES / 8, 128>>>(x, W, b, out);
    // one warp per edge: E warps -> E*32 threads
    k_scatter  <<<(N_EDGES * 32 + 255) / 256, 256>>>(ei, out);
}

// round 2
// speedup vs baseline: 2.2377x; 2.2377x over previous
#include <cuda_runtime.h>

#define N_NODES 100000
#define N_FEAT  128
#define N_EDGES 1600000
#define TILE_ROWS 64

// Scratch: degree, D^{-1/2}, transposed weights, staged features (51.2 MB).
__device__ float g_deg[N_NODES];
__device__ float g_dinv[N_NODES];
__device__ float g_WT[N_FEAT * N_FEAT];               // g_WT[k*128 + j] = W[j][k]
__device__ float g_xw[(size_t)N_NODES * N_FEAT];      // stores (x@W^T) * dinv[row]

// ---------------------------------------------------------------------------
__global__ void k_deg_init() {
    int i = blockIdx.x * blockDim.x + threadIdx.x;
    if (i < N_NODES) g_deg[i] = 1.0f;    // self-loop contributes 1
}

__global__ void k_deg_count(const int* __restrict__ col) {
    int e = blockIdx.x * blockDim.x + threadIdx.x;
    if (e < N_EDGES) atomicAdd(&g_deg[col[e]], 1.0f);
}

__global__ void k_dinv() {
    int i = blockIdx.x * blockDim.x + threadIdx.x;
    if (i < N_NODES) g_dinv[i] = rsqrtf(g_deg[i]);   // deg >= 1 always
}

// Transpose W (64KB, one-time per launch; cost is noise)
__global__ void k_wt(const float* __restrict__ W) {
    int idx = blockIdx.x * blockDim.x + threadIdx.x;   // 16384 elements
    int j = idx >> 7;          // row of W
    int k = idx & 127;         // col of W
    g_WT[k * N_FEAT + j] = W[idx];
}

// ---------------------------------------------------------------------------
// GEMM: out_tile = x_tile @ W^T, register tile 8 rows x 4 cols per thread.
// Block 256 threads covers 64 rows x 128 cols.
//   - x tile staged in 32KB smem, read as warp-broadcast (conflict-free)
//   - W^T read from global, warp-coalesced 512B lines, L1-resident (64KB)
// Epilogue: stage g_xw = acc*dinv[row]; out = acc*dinv^2 + bias (self-loop).
__global__ __launch_bounds__(256) void k_gemm(const float* __restrict__ x,
                                              const float* __restrict__ b,
                                              float* __restrict__ out) {
    __shared__ float xs[TILE_ROWS][N_FEAT];            // 32 KB
    const int t  = threadIdx.x;
    const int tx = t & 31;         // column group: cols tx*4 .. tx*4+3
    const int ty = t >> 5;         // row group:    rows ty*8 .. ty*8+7
    const int row0  = blockIdx.x * TILE_ROWS;
    const int nrows = min(TILE_ROWS, N_NODES - row0);

    // cooperative vectorized load of the x tile
    const float4* xsrc = reinterpret_cast<const float4*>(x + (size_t)row0 * N_FEAT);
    float4* xdst = reinterpret_cast<float4*>(&xs[0][0]);
    for (int idx = t; idx < nrows * (N_FEAT / 4); idx += 256) {
        xdst[idx] = xsrc[idx];
    }
    __syncthreads();

    float4 acc[8];
    #pragma unroll
    for (int r = 0; r < 8; ++r) acc[r] = make_float4(0.f, 0.f, 0.f, 0.f);

    #pragma unroll 4
    for (int k = 0; k < N_FEAT; k += 4) {
        float4 wv[4];
        #pragma unroll
        for (int kk = 0; kk < 4; ++kk)
            wv[kk] = *reinterpret_cast<const float4*>(&g_WT[(k + kk) * N_FEAT + tx * 4]);
        #pragma unroll
        for (int r = 0; r < 8; ++r) {
            const float4 xv = *reinterpret_cast<const float4*>(&xs[ty * 8 + r][k]);
            acc[r].x += xv.x * wv[0].x + xv.y * wv[1].x + xv.z * wv[2].x + xv.w * wv[3].x;
            acc[r].y += xv.x * wv[0].y + xv.y * wv[1].y + xv.z * wv[2].y + xv.w * wv[3].y;
            acc[r].z += xv.x * wv[0].z + xv.y * wv[1].z + xv.z * wv[2].z + xv.w * wv[3].z;
            acc[r].w += xv.x * wv[0].w + xv.y * wv[1].w + xv.z * wv[2].w + xv.w * wv[3].w;
        }
    }

    const float4 bv = reinterpret_cast<const float4*>(b)[tx];
    #pragma unroll
    for (int r = 0; r < 8; ++r) {
        const int row = row0 + ty * 8 + r;
        if (row < N_NODES) {
            const float di = g_dinv[row];
            const float s  = di * di;
            const float4 a = acc[r];
            float4 xw4 = make_float4(a.x * di, a.y * di, a.z * di, a.w * di);
            float4 o   = make_float4(a.x * s + bv.x, a.y * s + bv.y,
                                     a.z * s + bv.z, a.w * s + bv.w);
            reinterpret_cast<float4*>(g_xw + (size_t)row * N_FEAT)[tx] = xw4;
            reinterpret_cast<float4*>(out  + (size_t)row * N_FEAT)[tx] = o;
        }
    }
}

// ---------------------------------------------------------------------------
// Edge scatter: one warp per edge. g_xw already carries dinv[row]; only
// dinv[col] is applied here. Vector red.v4.f32 quarters the REDG lane-op count.
__global__ void k_scatter(const int* __restrict__ ei,
                          float* __restrict__ out) {
    const int gid  = blockIdx.x * blockDim.x + threadIdx.x;
    const int e    = gid >> 5;
    const int lane = threadIdx.x & 31;
    if (e >= N_EDGES) return;

    const int r = __ldg(&ei[e]);              // source
    const int c = __ldg(&ei[N_EDGES + e]);    // target
    const float nc = g_dinv[c];

    const float4 v = reinterpret_cast<const float4*>(g_xw + (size_t)r * N_FEAT)[lane];
    float* dst = out + (size_t)c * N_FEAT + lane * 4;
    asm volatile("red.global.add.v4.f32 [%0], {%1, %2, %3, %4};"
                 :: "l"(dst), "f"(v.x * nc), "f"(v.y * nc),
                    "f"(v.z * nc), "f"(v.w * nc)
                 : "memory");
}

// ---------------------------------------------------------------------------
extern "C" void kernel_launch(void* const* d_in, const int* in_sizes, int n_in,
                              void* d_out, int out_size) {
    const float* x  = (const float*)d_in[0];   // [100000, 128]
    const int*   ei = (const int*)  d_in[1];   // [2, 1600000]
    const float* W  = (const float*)d_in[2];   // [128, 128]
    const float* b  = (const float*)d_in[3];   // [128]
    float* out = (float*)d_out;                // [100000, 128]

    k_deg_init <<<(N_NODES + 255) / 256, 256>>>();
    k_deg_count<<<(N_EDGES + 255) / 256, 256>>>(ei + N_EDGES);
    k_wt       <<<(N_FEAT * N_FEAT) / 256, 256>>>(W);
    k_dinv     <<<(N_NODES + 255) / 256, 256>>>();
    k_gemm     <<<(N_NODES + TILE_ROWS - 1) / TILE_ROWS, 256>>>(x, b, out);
    k_scatter  <<<((size_t)N_EDGES * 32 + 255) / 256, 256>>>(ei, out);
}

// round 3
// speedup vs baseline: 3.4923x; 1.5607x over previous
#include <cuda_runtime.h>

#define N_NODES 100000
#define N_FEAT  128
#define N_EDGES 1600000
#define TILE_ROWS 64
#define SCAN_CHUNK 1024
#define NBLK ((N_NODES + SCAN_CHUNK - 1) / SCAN_CHUNK)   // 98

// Scratch buffers (__device__ globals: allocation-free).
__device__ int   g_degi[N_NODES];        // in-degree (without self loop)
__device__ int   g_rowstart[N_NODES];    // CSR offsets (exclusive scan of degi)
__device__ int   g_cursor[N_NODES];      // fill cursors
__device__ int   g_bsum[128];            // scan block sums
__device__ int   g_boff[128];            // scanned block offsets
__device__ int   g_srcs[N_EDGES];        // source ids grouped by target
__device__ float g_dinv[N_NODES];
__device__ float g_WT[N_FEAT * N_FEAT];              // WT[k*128+j] = W[j][k]
__device__ float g_xw[(size_t)N_NODES * N_FEAT];     // (x@W^T) * dinv[row]

// ---------------------------------------------------------------------------
__global__ void k_deg_init() {
    int i = blockIdx.x * blockDim.x + threadIdx.x;
    if (i < N_NODES) g_degi[i] = 0;
}

__global__ void k_deg_count(const int* __restrict__ col) {
    int e = blockIdx.x * blockDim.x + threadIdx.x;
    if (e < N_EDGES) atomicAdd(&g_degi[col[e]], 1);
}

__global__ void k_dinv() {
    int i = blockIdx.x * blockDim.x + threadIdx.x;
    if (i < N_NODES) g_dinv[i] = rsqrtf((float)(g_degi[i] + 1));  // +1 self loop
}

// --- exclusive scan of g_degi -> g_rowstart (3 stages) ----------------------
__global__ void k_scan1() {            // per-block scan of 1024-elem chunks
    __shared__ int sh[256];
    const int t = threadIdx.x;
    const int base = blockIdx.x * SCAN_CHUNK + t * 4;
    int v[4], s = 0;
    #pragma unroll
    for (int i = 0; i < 4; ++i) {
        int idx = base + i;
        v[i] = (idx < N_NODES) ? g_degi[idx] : 0;
        s += v[i];
    }
    sh[t] = s; __syncthreads();
    #pragma unroll
    for (int off = 1; off < 256; off <<= 1) {
        int add = (t >= off) ? sh[t - off] : 0;
        __syncthreads();
        sh[t] += add;
        __syncthreads();
    }
    if (t == 255) g_bsum[blockIdx.x] = sh[255];
    int run = sh[t] - s;               // exclusive prefix within block
    #pragma unroll
    for (int i = 0; i < 4; ++i) {
        int idx = base + i;
        if (idx < N_NODES) g_rowstart[idx] = run;
        run += v[i];
    }
}

__global__ void k_scan2() {            // scan the 98 block sums
    __shared__ int sh[128];
    const int t = threadIdx.x;
    int v = (t < NBLK) ? g_bsum[t] : 0;
    sh[t] = v; __syncthreads();
    #pragma unroll
    for (int off = 1; off < 128; off <<= 1) {
        int add = (t >= off) ? sh[t - off] : 0;
        __syncthreads();
        sh[t] += add;
        __syncthreads();
    }
    if (t < NBLK) g_boff[t] = sh[t] - v;
}

__global__ void k_scan3() {            // apply block offsets, init cursors
    int i = blockIdx.x * blockDim.x + threadIdx.x;
    if (i < N_NODES) {
        int rs = g_rowstart[i] + g_boff[i >> 10];
        g_rowstart[i] = rs;
        g_cursor[i]   = rs;
    }
}

// --- bucket-fill: group source ids by target --------------------------------
__global__ void k_fill(const int* __restrict__ ei) {
    int e = blockIdx.x * blockDim.x + threadIdx.x;
    if (e < N_EDGES) {
        int c = ei[N_EDGES + e];
        int pos = atomicAdd(&g_cursor[c], 1);
        g_srcs[pos] = ei[e];
    }
}

// ---------------------------------------------------------------------------
__global__ void k_wt(const float* __restrict__ W) {
    int idx = blockIdx.x * blockDim.x + threadIdx.x;
    int j = idx >> 7, k = idx & 127;
    g_WT[k * N_FEAT + j] = W[idx];
}

// GEMM: g_xw = (x @ W^T) * dinv[row].  8x4 register tile per thread.
__global__ __launch_bounds__(256) void k_gemm(const float* __restrict__ x) {
    __shared__ float xs[TILE_ROWS][N_FEAT];            // 32 KB
    const int t  = threadIdx.x;
    const int tx = t & 31;
    const int ty = t >> 5;
    const int row0  = blockIdx.x * TILE_ROWS;
    const int nrows = min(TILE_ROWS, N_NODES - row0);

    const float4* xsrc = reinterpret_cast<const float4*>(x + (size_t)row0 * N_FEAT);
    float4* xdst = reinterpret_cast<float4*>(&xs[0][0]);
    for (int idx = t; idx < nrows * (N_FEAT / 4); idx += 256) xdst[idx] = xsrc[idx];
    __syncthreads();

    float4 acc[8];
    #pragma unroll
    for (int r = 0; r < 8; ++r) acc[r] = make_float4(0.f, 0.f, 0.f, 0.f);

    #pragma unroll 4
    for (int k = 0; k < N_FEAT; k += 4) {
        float4 wv[4];
        #pragma unroll
        for (int kk = 0; kk < 4; ++kk)
            wv[kk] = *reinterpret_cast<const float4*>(&g_WT[(k + kk) * N_FEAT + tx * 4]);
        #pragma unroll
        for (int r = 0; r < 8; ++r) {
            const float4 xv = *reinterpret_cast<const float4*>(&xs[ty * 8 + r][k]);
            acc[r].x += xv.x * wv[0].x + xv.y * wv[1].x + xv.z * wv[2].x + xv.w * wv[3].x;
            acc[r].y += xv.x * wv[0].y + xv.y * wv[1].y + xv.z * wv[2].y + xv.w * wv[3].y;
            acc[r].z += xv.x * wv[0].z + xv.y * wv[1].z + xv.z * wv[2].z + xv.w * wv[3].z;
            acc[r].w += xv.x * wv[0].w + xv.y * wv[1].w + xv.z * wv[2].w + xv.w * wv[3].w;
        }
    }

    #pragma unroll
    for (int r = 0; r < 8; ++r) {
        const int row = row0 + ty * 8 + r;
        if (row < N_NODES) {
            const float di = g_dinv[row];
            const float4 a = acc[r];
            reinterpret_cast<float4*>(g_xw + (size_t)row * N_FEAT)[tx] =
                make_float4(a.x * di, a.y * di, a.z * di, a.w * di);
        }
    }
}

// ---------------------------------------------------------------------------
// Pull aggregation: one warp per target node.
// out[c] = (sum_{s in in(c)} g_xw[s] + g_xw[c]) * dinv[c] + b
__global__ __launch_bounds__(256) void k_gather(const float* __restrict__ b,
                                                float* __restrict__ out) {
    const int warp = (blockIdx.x * blockDim.x + threadIdx.x) >> 5;
    const int lane = threadIdx.x & 31;
    if (warp >= N_NODES) return;
    const int c = warp;

    const int base = g_rowstart[c];
    const int cnt  = g_degi[c];

    float4 a0 = make_float4(0.f,0.f,0.f,0.f), a1 = a0, a2 = a0, a3 = a0;
    const float4* xw = reinterpret_cast<const float4*>(g_xw);

    int i = 0;
    for (; i + 4 <= cnt; i += 4) {
        const int s0 = g_srcs[base + i + 0];
        const int s1 = g_srcs[base + i + 1];
        const int s2 = g_srcs[base + i + 2];
        const int s3 = g_srcs[base + i + 3];
        const float4 v0 = xw[(size_t)s0 * 32 + lane];
        const float4 v1 = xw[(size_t)s1 * 32 + lane];
        const float4 v2 = xw[(size_t)s2 * 32 + lane];
        const float4 v3 = xw[(size_t)s3 * 32 + lane];
        a0.x += v0.x; a0.y += v0.y; a0.z += v0.z; a0.w += v0.w;
        a1.x += v1.x; a1.y += v1.y; a1.z += v1.z; a1.w += v1.w;
        a2.x += v2.x; a2.y += v2.y; a2.z += v2.z; a2.w += v2.w;
        a3.x += v3.x; a3.y += v3.y; a3.z += v3.z; a3.w += v3.w;
    }
    for (; i < cnt; ++i) {
        const int s = g_srcs[base + i];
        const float4 v = xw[(size_t)s * 32 + lane];
        a0.x += v.x; a0.y += v.y; a0.z += v.z; a0.w += v.w;
    }

    const float4 self = xw[(size_t)c * 32 + lane];
    float4 acc = make_float4(a0.x + a1.x + a2.x + a3.x + self.x,
                             a0.y + a1.y + a2.y + a3.y + self.y,
                             a0.z + a1.z + a2.z + a3.z + self.z,
                             a0.w + a1.w + a2.w + a3.w + self.w);
    const float nc = g_dinv[c];
    const float4 bv = reinterpret_cast<const float4*>(b)[lane];
    reinterpret_cast<float4*>(out + (size_t)c * N_FEAT)[lane] =
        make_float4(acc.x * nc + bv.x, acc.y * nc + bv.y,
                    acc.z * nc + bv.z, acc.w * nc + bv.w);
}

// ---------------------------------------------------------------------------
extern "C" void kernel_launch(void* const* d_in, const int* in_sizes, int n_in,
                              void* d_out, int out_size) {
    const float* x  = (const float*)d_in[0];
    const int*   ei = (const int*)  d_in[1];
    const float* W  = (const float*)d_in[2];
    const float* b  = (const float*)d_in[3];
    float* out = (float*)d_out;

    k_deg_init <<<(N_NODES + 255) / 256, 256>>>();
    k_deg_count<<<(N_EDGES + 255) / 256, 256>>>(ei + N_EDGES);
    k_dinv     <<<(N_NODES + 255) / 256, 256>>>();
    k_scan1    <<<NBLK, 256>>>();
    k_scan2    <<<1, 128>>>();
    k_scan3    <<<(N_NODES + 255) / 256, 256>>>();
    k_fill     <<<(N_EDGES + 255) / 256, 256>>>(ei);
    k_wt       <<<(N_FEAT * N_FEAT) / 256, 256>>>(W);
    k_gemm     <<<(N_NODES + TILE_ROWS - 1) / TILE_ROWS, 256>>>(x);
    k_gather   <<<(N_NODES * 32 + 255) / 256, 256>>>(b, out);
}

// round 4
// speedup vs baseline: 3.7989x; 1.0878x over previous
#include <cuda_runtime.h>
#include <cstdint>

#define N_NODES 100000
#define N_FEAT  128
#define N_EDGES 1600000
#define SCAN_CHUNK 1024
#define NBLK ((N_NODES + SCAN_CHUNK - 1) / SCAN_CHUNK)   // 98

// Scratch buffers (__device__ globals: allocation-free).
__device__ int   g_degi[N_NODES];
__device__ int   g_rowstart[N_NODES];
__device__ int   g_cursor[N_NODES];
__device__ int   g_bsum[128];
__device__ int   g_boff[128];
__device__ int   g_srcs[N_EDGES];
__device__ float g_dinv[N_NODES];
__device__ float g_Bfrag[16 * 16 * 32 * 4];          // W fragments {hi0,hi1,lo0,lo1}
__device__ float g_xw[(size_t)N_NODES * N_FEAT];     // (x@W^T) * dinv[row]

__device__ __forceinline__ uint32_t tf32_hi(float v) {
    return __float_as_uint(v) & 0xffffe000u;
}

// ---------------------------------------------------------------------------
__global__ void k_deg_init() {
    int i = blockIdx.x * blockDim.x + threadIdx.x;
    if (i < N_NODES) g_degi[i] = 0;
}

__global__ void k_deg_count(const int* __restrict__ col) {
    int e = blockIdx.x * blockDim.x + threadIdx.x;
    if (e < N_EDGES) atomicAdd(&g_degi[col[e]], 1);
}

// --- scan stage 1 (also computes dinv, since it reads degi anyway) ----------
__global__ void k_scan1() {
    __shared__ int sh[256];
    const int t = threadIdx.x;
    const int base = blockIdx.x * SCAN_CHUNK + t * 4;
    int v[4], s = 0;
    #pragma unroll
    for (int i = 0; i < 4; ++i) {
        int idx = base + i;
        v[i] = (idx < N_NODES) ? g_degi[idx] : 0;
        if (idx < N_NODES) g_dinv[idx] = rsqrtf((float)(v[i] + 1));
        s += v[i];
    }
    sh[t] = s; __syncthreads();
    #pragma unroll
    for (int off = 1; off < 256; off <<= 1) {
        int add = (t >= off) ? sh[t - off] : 0;
        __syncthreads();
        sh[t] += add;
        __syncthreads();
    }
    if (t == 255) g_bsum[blockIdx.x] = sh[255];
    int run = sh[t] - s;
    #pragma unroll
    for (int i = 0; i < 4; ++i) {
        int idx = base + i;
        if (idx < N_NODES) g_rowstart[idx] = run;
        run += v[i];
    }
}

__global__ void k_scan2() {
    __shared__ int sh[128];
    const int t = threadIdx.x;
    int v = (t < NBLK) ? g_bsum[t] : 0;
    sh[t] = v; __syncthreads();
    #pragma unroll
    for (int off = 1; off < 128; off <<= 1) {
        int add = (t >= off) ? sh[t - off] : 0;
        __syncthreads();
        sh[t] += add;
        __syncthreads();
    }
    if (t < NBLK) g_boff[t] = sh[t] - v;
}

__global__ void k_scan3() {
    int i = blockIdx.x * blockDim.x + threadIdx.x;
    if (i < N_NODES) {
        int rs = g_rowstart[i] + g_boff[i >> 10];
        g_rowstart[i] = rs;
        g_cursor[i]   = rs;
    }
}

__global__ void k_fill(const int* __restrict__ ei) {
    int e = blockIdx.x * blockDim.x + threadIdx.x;
    if (e < N_EDGES) {
        int c = ei[N_EDGES + e];
        int pos = atomicAdd(&g_cursor[c], 1);
        g_srcs[pos] = ei[e];
    }
}

// ---------------------------------------------------------------------------
// Precompute W as tf32 B-fragments (hi/lo split) in mma fragment order so the
// GEMM mainloop does one coalesced LDG.128 per (k,n) chunk.
// B frag (k8 x n8, col): b0 -> (k = lane%4,     n = lane/4)
//                        b1 -> (k = lane%4 + 4, n = lane/4)
__global__ void k_wfrag(const float* __restrict__ W) {
    const int t = blockIdx.x * blockDim.x + threadIdx.x;   // 8192 total
    if (t >= 16 * 16 * 32) return;
    const int lane = t & 31;
    const int nc   = (t >> 5) & 15;
    const int kc   = t >> 9;
    const int k = kc * 8 + (lane & 3);
    const int n = nc * 8 + (lane >> 2);
    // W^T[k][n] = W[n][k]
    const float b0 = W[n * N_FEAT + k];
    const float b1 = W[n * N_FEAT + k + 4];
    const uint32_t h0 = tf32_hi(b0), h1 = tf32_hi(b1);
    const float l0 = b0 - __uint_as_float(h0);
    const float l1 = b1 - __uint_as_float(h1);
    reinterpret_cast<float4*>(g_Bfrag)[t] =
        make_float4(__uint_as_float(h0), __uint_as_float(h1), l0, l1);
}

#define MMA_TF32(acc, a0, a1, a2, a3, b0, b1)                                  \
    asm volatile("mma.sync.aligned.m16n8k8.row.col.f32.tf32.tf32.f32 "         \
                 "{%0,%1,%2,%3}, {%4,%5,%6,%7}, {%8,%9}, {%0,%1,%2,%3};"       \
                 : "+f"(acc[0]), "+f"(acc[1]), "+f"(acc[2]), "+f"(acc[3])      \
                 : "r"(a0), "r"(a1), "r"(a2), "r"(a3), "r"(b0), "r"(b1))

// Tensor GEMM: g_xw = (x @ W^T) * dinv[row].
// Block = 128 threads (4 warps), tile M=64 (16 rows/warp), N=128.
// 3-term tf32 split: acc += Ahi*Bhi + Ahi*Blo + Alo*Bhi  (lo*lo dropped).
__global__ __launch_bounds__(128) void k_gemm(const float* __restrict__ x) {
    __shared__ float xs[64][132];                      // pad 132: conflict-free frags
    const int t    = threadIdx.x;
    const int warp = t >> 5;
    const int lane = t & 31;
    const int row0  = blockIdx.x * 64;
    const int nrows = min(64, N_NODES - row0);

    const float4* src = reinterpret_cast<const float4*>(x + (size_t)row0 * N_FEAT);
    for (int idx = t; idx < nrows * 32; idx += 128) {
        const int r = idx >> 5, c4 = idx & 31;
        *reinterpret_cast<float4*>(&xs[r][c4 * 4]) = src[idx];
    }
    __syncthreads();

    const int g  = lane >> 2;       // group id 0..7
    const int tg = lane & 3;        // thread-in-group 0..3
    const int rb = warp * 16;

    float acc[16][4];
    #pragma unroll
    for (int nc = 0; nc < 16; ++nc)
        acc[nc][0] = acc[nc][1] = acc[nc][2] = acc[nc][3] = 0.f;

    const float4* bfrag = reinterpret_cast<const float4*>(g_Bfrag);

    for (int kc = 0; kc < 16; ++kc) {
        const int k0 = kc * 8;
        // A fragment (raw), then hi/lo split
        const float ar0 = xs[rb + g][k0 + tg];
        const float ar1 = xs[rb + g + 8][k0 + tg];
        const float ar2 = xs[rb + g][k0 + tg + 4];
        const float ar3 = xs[rb + g + 8][k0 + tg + 4];
        const uint32_t h0 = tf32_hi(ar0), h1 = tf32_hi(ar1);
        const uint32_t h2 = tf32_hi(ar2), h3 = tf32_hi(ar3);
        const uint32_t l0 = __float_as_uint(ar0 - __uint_as_float(h0));
        const uint32_t l1 = __float_as_uint(ar1 - __uint_as_float(h1));
        const uint32_t l2 = __float_as_uint(ar2 - __uint_as_float(h2));
        const uint32_t l3 = __float_as_uint(ar3 - __uint_as_float(h3));

        #pragma unroll
        for (int nc = 0; nc < 16; ++nc) {
            const float4 b = bfrag[((kc << 4) + nc) * 32 + lane];
            const uint32_t bh0 = __float_as_uint(b.x), bh1 = __float_as_uint(b.y);
            const uint32_t bl0 = __float_as_uint(b.z), bl1 = __float_as_uint(b.w);
            MMA_TF32(acc[nc], h0, h1, h2, h3, bh0, bh1);   // hi*hi
            MMA_TF32(acc[nc], h0, h1, h2, h3, bl0, bl1);   // hi*lo
            MMA_TF32(acc[nc], l0, l1, l2, l3, bh0, bh1);   // lo*hi
        }
    }

    // Epilogue: C frag c0/c1 -> (row0+g, tg*2 [+1]); c2/c3 -> (+8 rows)
    const int r0 = row0 + rb + g;
    const int r1 = r0 + 8;
    const float d0 = (r0 < N_NODES) ? g_dinv[r0] : 0.f;
    const float d1 = (r1 < N_NODES) ? g_dinv[r1] : 0.f;
    #pragma unroll
    for (int nc = 0; nc < 16; ++nc) {
        const int col = nc * 8 + tg * 2;
        if (r0 < N_NODES)
            *reinterpret_cast<float2*>(g_xw + (size_t)r0 * N_FEAT + col) =
                make_float2(acc[nc][0] * d0, acc[nc][1] * d0);
        if (r1 < N_NODES)
            *reinterpret_cast<float2*>(g_xw + (size_t)r1 * N_FEAT + col) =
                make_float2(acc[nc][2] * d1, acc[nc][3] * d1);
    }
}

// ---------------------------------------------------------------------------
// Pull aggregation: one warp per target node (unchanged from R3 — known good).
__global__ __launch_bounds__(256) void k_gather(const float* __restrict__ b,
                                                float* __restrict__ out) {
    const int warp = (blockIdx.x * blockDim.x + threadIdx.x) >> 5;
    const int lane = threadIdx.x & 31;
    if (warp >= N_NODES) return;
    const int c = warp;

    const int base = g_rowstart[c];
    const int cnt  = g_degi[c];

    float4 a0 = make_float4(0.f,0.f,0.f,0.f), a1 = a0, a2 = a0, a3 = a0;
    const float4* xw = reinterpret_cast<const float4*>(g_xw);

    int i = 0;
    for (; i + 4 <= cnt; i += 4) {
        const int s0 = g_srcs[base + i + 0];
        const int s1 = g_srcs[base + i + 1];
        const int s2 = g_srcs[base + i + 2];
        const int s3 = g_srcs[base + i + 3];
        const float4 v0 = xw[(size_t)s0 * 32 + lane];
        const float4 v1 = xw[(size_t)s1 * 32 + lane];
        const float4 v2 = xw[(size_t)s2 * 32 + lane];
        const float4 v3 = xw[(size_t)s3 * 32 + lane];
        a0.x += v0.x; a0.y += v0.y; a0.z += v0.z; a0.w += v0.w;
        a1.x += v1.x; a1.y += v1.y; a1.z += v1.z; a1.w += v1.w;
        a2.x += v2.x; a2.y += v2.y; a2.z += v2.z; a2.w += v2.w;
        a3.x += v3.x; a3.y += v3.y; a3.z += v3.z; a3.w += v3.w;
    }
    for (; i < cnt; ++i) {
        const int s = g_srcs[base + i];
        const float4 v = xw[(size_t)s * 32 + lane];
        a0.x += v.x; a0.y += v.y; a0.z += v.z; a0.w += v.w;
    }

    const float4 self = xw[(size_t)c * 32 + lane];
    float4 acc = make_float4(a0.x + a1.x + a2.x + a3.x + self.x,
                             a0.y + a1.y + a2.y + a3.y + self.y,
                             a0.z + a1.z + a2.z + a3.z + self.z,
                             a0.w + a1.w + a2.w + a3.w + self.w);
    const float nc = g_dinv[c];
    const float4 bv = reinterpret_cast<const float4*>(b)[lane];
    reinterpret_cast<float4*>(out + (size_t)c * N_FEAT)[lane] =
        make_float4(acc.x * nc + bv.x, acc.y * nc + bv.y,
                    acc.z * nc + bv.z, acc.w * nc + bv.w);
}

// ---------------------------------------------------------------------------
extern "C" void kernel_launch(void* const* d_in, const int* in_sizes, int n_in,
                              void* d_out, int out_size) {
    const float* x  = (const float*)d_in[0];
    const int*   ei = (const int*)  d_in[1];
    const float* W  = (const float*)d_in[2];
    const float* b  = (const float*)d_in[3];
    float* out = (float*)d_out;

    k_deg_init <<<(N_NODES + 255) / 256, 256>>>();
    k_deg_count<<<(N_EDGES + 255) / 256, 256>>>(ei + N_EDGES);
    k_scan1    <<<NBLK, 256>>>();
    k_scan2    <<<1, 128>>>();
    k_scan3    <<<(N_NODES + 255) / 256, 256>>>();
    k_fill     <<<(N_EDGES + 255) / 256, 256>>>(ei);
    k_wfrag    <<<(16 * 16 * 32 + 255) / 256, 256>>>(W);
    k_gemm     <<<(N_NODES + 63) / 64, 128>>>(x);
    k_gather   <<<(N_NODES * 32 + 255) / 256, 256>>>(b, out);
}

// round 6
// speedup vs baseline: 4.1537x; 1.0934x over previous
#include <cuda_runtime.h>
#include <cstdint>

#define N_NODES 100000
#define N_FEAT  128
#define N_EDGES 1600000
#define SCAN_CHUNK 1024
#define NBLK ((N_NODES + SCAN_CHUNK - 1) / SCAN_CHUNK)   // 98

// Scratch (__device__ globals: allocation-free).
__device__ int   g_degi[N_NODES];
__device__ int   g_rowstart[N_NODES];
__device__ int   g_cursor[N_NODES];
__device__ int   g_bsum[128];
__device__ int   g_srcs[N_EDGES];
__device__ float g_dinv[N_NODES];
__device__ float g_Bfrag[16 * 16 * 32 * 2];          // W hi fragments {hi0,hi1}
__device__ float g_xw[(size_t)N_NODES * N_FEAT];     // (x@W^T) * dinv[row]

__device__ __forceinline__ uint32_t tf32_rna(float v) {
    uint32_t r;
    asm("cvt.rna.tf32.f32 %0, %1;" : "=r"(r) : "f"(v));
    return r;
}

// ---------------------------------------------------------------------------
// 1) fused: zero degree counters + pack W hi-fragments (independent work)
//    B frag (k8 x n8, col-major): b0 -> (k=lane%4, n=lane/4), b1 -> (k+4, n)
__global__ void k_init_bpack(const float* __restrict__ W) {
    const int t = blockIdx.x * blockDim.x + threadIdx.x;
    if (t < N_NODES) g_degi[t] = 0;
    if (t < 16 * 16 * 32) {
        const int lane = t & 31;
        const int nc   = (t >> 5) & 15;
        const int kc   = t >> 9;
        const int k = kc * 8 + (lane & 3);
        const int n = nc * 8 + (lane >> 2);
        const uint32_t h0 = tf32_rna(W[n * N_FEAT + k]);      // W^T[k][n]
        const uint32_t h1 = tf32_rna(W[n * N_FEAT + k + 4]);
        reinterpret_cast<float2*>(g_Bfrag)[t] =
            make_float2(__uint_as_float(h0), __uint_as_float(h1));
    }
}

// 2) degree count
__global__ void k_deg_count(const int* __restrict__ col) {
    int e = blockIdx.x * blockDim.x + threadIdx.x;
    if (e < N_EDGES) atomicAdd(&g_degi[col[e]], 1);
}

// 3) scan stage 1 (+ dinv, since it reads degi anyway)
__global__ void k_scan1() {
    __shared__ int sh[256];
    const int t = threadIdx.x;
    const int base = blockIdx.x * SCAN_CHUNK + t * 4;
    int v[4], s = 0;
    #pragma unroll
    for (int i = 0; i < 4; ++i) {
        int idx = base + i;
        v[i] = (idx < N_NODES) ? g_degi[idx] : 0;
        if (idx < N_NODES) g_dinv[idx] = rsqrtf((float)(v[i] + 1));
        s += v[i];
    }
    sh[t] = s; __syncthreads();
    #pragma unroll
    for (int off = 1; off < 256; off <<= 1) {
        int add = (t >= off) ? sh[t - off] : 0;
        __syncthreads();
        sh[t] += add;
        __syncthreads();
    }
    if (t == 255) g_bsum[blockIdx.x] = sh[255];
    int run = sh[t] - s;
    #pragma unroll
    for (int i = 0; i < 4; ++i) {
        int idx = base + i;
        if (idx < N_NODES) g_rowstart[idx] = run;
        run += v[i];
    }
}

// ---------------------------------------------------------------------------
#define MMA_TF32(acc, a0, a1, a2, a3, b0, b1)                                  \
    asm volatile("mma.sync.aligned.m16n8k8.row.col.f32.tf32.tf32.f32 "         \
                 "{%0,%1,%2,%3}, {%4,%5,%6,%7}, {%8,%9}, {%0,%1,%2,%3};"       \
                 : "+f"(acc[0]), "+f"(acc[1]), "+f"(acc[2]), "+f"(acc[3])      \
                 : "r"(a0), "r"(a1), "r"(a2), "r"(a3), "r"(b0), "r"(b1))

// 4) GEMM (profiled launch): g_xw = (x @ W^T) * dinv[row].
//    2-term tf32 split: acc += Ahi*Bhi + Alo*Bhi  (rna rounding on hi).
//    Block = 128 threads (4 warps), tile M=64 (16 rows/warp), N=128.
__global__ __launch_bounds__(128) void k_gemm(const float* __restrict__ x) {
    __shared__ float xs[64][132];                      // pad 132: conflict-free
    const int t    = threadIdx.x;
    const int warp = t >> 5;
    const int lane = t & 31;
    const int row0  = blockIdx.x * 64;
    const int nrows = min(64, N_NODES - row0);

    const float4* src = reinterpret_cast<const float4*>(x + (size_t)row0 * N_FEAT);
    for (int idx = t; idx < nrows * 32; idx += 128) {
        const int r = idx >> 5, c4 = idx & 31;
        *reinterpret_cast<float4*>(&xs[r][c4 * 4]) = src[idx];
    }
    __syncthreads();

    const int g  = lane >> 2;       // group id 0..7
    const int tg = lane & 3;        // thread-in-group 0..3
    const int rb = warp * 16;

    float acc[16][4];
    #pragma unroll
    for (int nc = 0; nc < 16; ++nc)
        acc[nc][0] = acc[nc][1] = acc[nc][2] = acc[nc][3] = 0.f;

    const float2* bfrag = reinterpret_cast<const float2*>(g_Bfrag);

    for (int kc = 0; kc < 16; ++kc) {
        const int k0 = kc * 8;
        const float ar0 = xs[rb + g][k0 + tg];
        const float ar1 = xs[rb + g + 8][k0 + tg];
        const float ar2 = xs[rb + g][k0 + tg + 4];
        const float ar3 = xs[rb + g + 8][k0 + tg + 4];
        const uint32_t h0 = tf32_rna(ar0), h1 = tf32_rna(ar1);
        const uint32_t h2 = tf32_rna(ar2), h3 = tf32_rna(ar3);
        const uint32_t l0 = __float_as_uint(ar0 - __uint_as_float(h0));
        const uint32_t l1 = __float_as_uint(ar1 - __uint_as_float(h1));
        const uint32_t l2 = __float_as_uint(ar2 - __uint_as_float(h2));
        const uint32_t l3 = __float_as_uint(ar3 - __uint_as_float(h3));

        #pragma unroll
        for (int nc = 0; nc < 16; ++nc) {
            const float2 b = bfrag[((kc << 4) + nc) * 32 + lane];
            const uint32_t bh0 = __float_as_uint(b.x), bh1 = __float_as_uint(b.y);
            MMA_TF32(acc[nc], h0, h1, h2, h3, bh0, bh1);   // hi*hi
            MMA_TF32(acc[nc], l0, l1, l2, l3, bh0, bh1);   // lo*hi
        }
    }

    // Epilogue: C frag c0/c1 -> (row0+g, tg*2 [+1]); c2/c3 -> (+8 rows)
    const int r0 = row0 + rb + g;
    const int r1 = r0 + 8;
    const float d0 = (r0 < N_NODES) ? g_dinv[r0] : 0.f;
    const float d1 = (r1 < N_NODES) ? g_dinv[r1] : 0.f;
    #pragma unroll
    for (int nc = 0; nc < 16; ++nc) {
        const int col = nc * 8 + tg * 2;
        if (r0 < N_NODES)
            *reinterpret_cast<float2*>(g_xw + (size_t)r0 * N_FEAT + col) =
                make_float2(acc[nc][0] * d0, acc[nc][1] * d0);
        if (r1 < N_NODES)
            *reinterpret_cast<float2*>(g_xw + (size_t)r1 * N_FEAT + col) =
                make_float2(acc[nc][2] * d1, acc[nc][3] * d1);
    }
}

// 5) fused scan stages 2+3: every block redundantly scans the 98 block sums
__global__ void k_scan23() {
    __shared__ int sh[128];
    const int t = threadIdx.x;
    int v = 0;
    if (t < 128) { v = (t < NBLK) ? g_bsum[t] : 0; sh[t] = v; }
    __syncthreads();
    #pragma unroll
    for (int off = 1; off < 128; off <<= 1) {
        int add = 0;
        if (t < 128 && t >= off) add = sh[t - off];
        __syncthreads();
        if (t < 128) sh[t] += add;
        __syncthreads();
    }
    if (t < 128) sh[t] -= v;          // exclusive block offsets
    __syncthreads();
    const int i = blockIdx.x * blockDim.x + t;
    if (i < N_NODES) {
        int rs = g_rowstart[i] + sh[i >> 10];
        g_rowstart[i] = rs;
        g_cursor[i]   = rs;
    }
}

// 6) bucket-fill: group source ids by target
__global__ void k_fill(const int* __restrict__ ei) {
    int e = blockIdx.x * blockDim.x + threadIdx.x;
    if (e < N_EDGES) {
        int c = ei[N_EDGES + e];
        int pos = atomicAdd(&g_cursor[c], 1);
        g_srcs[pos] = ei[e];
    }
}

// ---------------------------------------------------------------------------
// 7) Pull aggregation: one warp per target node. xw pre-scaled by dinv[row].
__global__ __launch_bounds__(256) void k_gather(const float* __restrict__ b,
                                                float* __restrict__ out) {
    const int warp = (blockIdx.x * blockDim.x + threadIdx.x) >> 5;
    const int lane = threadIdx.x & 31;
    if (warp >= N_NODES) return;
    const int c = warp;

    const int base = g_rowstart[c];
    const int cnt  = g_degi[c];

    float4 a0 = make_float4(0.f,0.f,0.f,0.f), a1 = a0, a2 = a0, a3 = a0;
    const float4* xw = reinterpret_cast<const float4*>(g_xw);

    int i = 0;
    for (; i + 4 <= cnt; i += 4) {
        const int s0 = g_srcs[base + i + 0];
        const int s1 = g_srcs[base + i + 1];
        const int s2 = g_srcs[base + i + 2];
        const int s3 = g_srcs[base + i + 3];
        const float4 v0 = xw[(size_t)s0 * 32 + lane];
        const float4 v1 = xw[(size_t)s1 * 32 + lane];
        const float4 v2 = xw[(size_t)s2 * 32 + lane];
        const float4 v3 = xw[(size_t)s3 * 32 + lane];
        a0.x += v0.x; a0.y += v0.y; a0.z += v0.z; a0.w += v0.w;
        a1.x += v1.x; a1.y += v1.y; a1.z += v1.z; a1.w += v1.w;
        a2.x += v2.x; a2.y += v2.y; a2.z += v2.z; a2.w += v2.w;
        a3.x += v3.x; a3.y += v3.y; a3.z += v3.z; a3.w += v3.w;
    }
    for (; i < cnt; ++i) {
        const int s = g_srcs[base + i];
        const float4 v = xw[(size_t)s * 32 + lane];
        a0.x += v.x; a0.y += v.y; a0.z += v.z; a0.w += v.w;
    }

    const float4 self = xw[(size_t)c * 32 + lane];
    float4 acc = make_float4(a0.x + a1.x + a2.x + a3.x + self.x,
                             a0.y + a1.y + a2.y + a3.y + self.y,
                             a0.z + a1.z + a2.z + a3.z + self.z,
                             a0.w + a1.w + a2.w + a3.w + self.w);
    const float nc = g_dinv[c];
    const float4 bv = reinterpret_cast<const float4*>(b)[lane];
    reinterpret_cast<float4*>(out + (size_t)c * N_FEAT)[lane] =
        make_float4(acc.x * nc + bv.x, acc.y * nc + bv.y,
                    acc.z * nc + bv.z, acc.w * nc + bv.w);
}

// ---------------------------------------------------------------------------
extern "C" void kernel_launch(void* const* d_in, const int* in_sizes, int n_in,
                              void* d_out, int out_size) {
    const float* x  = (const float*)d_in[0];
    const int*   ei = (const int*)  d_in[1];
    const float* W  = (const float*)d_in[2];
    const float* b  = (const float*)d_in[3];
    float* out = (float*)d_out;

    k_init_bpack<<<(N_NODES + 255) / 256, 256>>>(W);               // 1
    k_deg_count <<<(N_EDGES + 255) / 256, 256>>>(ei + N_EDGES);    // 2
    k_scan1     <<<NBLK, 256>>>();                                 // 3 (dinv ready)
    k_gemm      <<<(N_NODES + 63) / 64, 128>>>(x);                 // 4 (profiled)
    k_scan23    <<<(N_NODES + 255) / 256, 256>>>();                // 5
    k_fill      <<<(N_EDGES + 255) / 256, 256>>>(ei);              // 6
    k_gather    <<<(N_NODES * 32 + 255) / 256, 256>>>(b, out);     // 7
}

// round 7
// speedup vs baseline: 4.4212x; 1.0644x over previous
#include <cuda_runtime.h>
#include <cstdint>

#define N_NODES 100000
#define N_FEAT  128
#define N_EDGES 1600000
#define SCAN_CHUNK 1024
#define NBLK ((N_NODES + SCAN_CHUNK - 1) / SCAN_CHUNK)   // 98

// Scratch (__device__ globals: allocation-free).
__device__ int   g_degi[N_NODES];
__device__ int   g_rowstart[N_NODES];
__device__ int   g_cursor[N_NODES];
__device__ int   g_bsum[128];
__device__ int   g_srcs[N_EDGES];
__device__ float g_dinv[N_NODES];
__device__ float g_Bfrag[16 * 16 * 32 * 2];          // W hi fragments {hi0,hi1}
__device__ float g_xw[(size_t)N_NODES * N_FEAT];     // (x@W^T) * dinv[row]

__device__ __forceinline__ uint32_t tf32_rna(float v) {
    uint32_t r;
    asm("cvt.rna.tf32.f32 %0, %1;" : "=r"(r) : "f"(v));
    return r;
}

// ---------------------------------------------------------------------------
// 1) fused: zero degree counters + pack W hi-fragments
//    B frag (k8 x n8, col-major): b0 -> (k=lane%4, n=lane/4), b1 -> (k+4, n)
__global__ void k_init_bpack(const float* __restrict__ W) {
    const int t = blockIdx.x * blockDim.x + threadIdx.x;
    if (t < N_NODES) g_degi[t] = 0;
    if (t < 16 * 16 * 32) {
        const int lane = t & 31;
        const int nc   = (t >> 5) & 15;
        const int kc   = t >> 9;
        const int k = kc * 8 + (lane & 3);
        const int n = nc * 8 + (lane >> 2);
        const uint32_t h0 = tf32_rna(W[n * N_FEAT + k]);      // W^T[k][n]
        const uint32_t h1 = tf32_rna(W[n * N_FEAT + k + 4]);
        reinterpret_cast<float2*>(g_Bfrag)[t] =
            make_float2(__uint_as_float(h0), __uint_as_float(h1));
    }
}

// 2) degree count
__global__ void k_deg_count(const int* __restrict__ col) {
    int e = blockIdx.x * blockDim.x + threadIdx.x;
    if (e < N_EDGES) atomicAdd(&g_degi[col[e]], 1);
}

// 3) scan stage 1 (+ dinv)
__global__ void k_scan1() {
    __shared__ int sh[256];
    const int t = threadIdx.x;
    const int base = blockIdx.x * SCAN_CHUNK + t * 4;
    int v[4], s = 0;
    #pragma unroll
    for (int i = 0; i < 4; ++i) {
        int idx = base + i;
        v[i] = (idx < N_NODES) ? g_degi[idx] : 0;
        if (idx < N_NODES) g_dinv[idx] = rsqrtf((float)(v[i] + 1));
        s += v[i];
    }
    sh[t] = s; __syncthreads();
    #pragma unroll
    for (int off = 1; off < 256; off <<= 1) {
        int add = (t >= off) ? sh[t - off] : 0;
        __syncthreads();
        sh[t] += add;
        __syncthreads();
    }
    if (t == 255) g_bsum[blockIdx.x] = sh[255];
    int run = sh[t] - s;
    #pragma unroll
    for (int i = 0; i < 4; ++i) {
        int idx = base + i;
        if (idx < N_NODES) g_rowstart[idx] = run;
        run += v[i];
    }
}

// ---------------------------------------------------------------------------
#define MMA_TF32(acc, a0, a1, a2, a3, b0, b1)                                  \
    asm volatile("mma.sync.aligned.m16n8k8.row.col.f32.tf32.tf32.f32 "         \
                 "{%0,%1,%2,%3}, {%4,%5,%6,%7}, {%8,%9}, {%0,%1,%2,%3};"       \
                 : "+f"(acc[0]), "+f"(acc[1]), "+f"(acc[2]), "+f"(acc[3])      \
                 : "r"(a0), "r"(a1), "r"(a2), "r"(a3), "r"(b0), "r"(b1))

// 4) GEMM (profiled launch): g_xw = (x @ W^T) * dinv[row].
//    2-term tf32 split. Block = 256 threads / 8 warps.
//    Warp tile: 16 rows x 64 cols -> acc = 32 regs/thread (occupancy up),
//    B fragments prefetched with distance 1 (breaks LDG->MMA chain).
__global__ __launch_bounds__(256) void k_gemm(const float* __restrict__ x) {
    __shared__ float xs[64][132];                      // pad 132: conflict-free
    const int t    = threadIdx.x;
    const int warp = t >> 5;
    const int lane = t & 31;
    const int row0  = blockIdx.x * 64;
    const int nrows = min(64, N_NODES - row0);

    const float4* src = reinterpret_cast<const float4*>(x + (size_t)row0 * N_FEAT);
    for (int idx = t; idx < nrows * 32; idx += 256) {
        const int r = idx >> 5, c4 = idx & 31;
        *reinterpret_cast<float4*>(&xs[r][c4 * 4]) = src[idx];
    }
    __syncthreads();

    const int g   = lane >> 2;        // group id 0..7
    const int tg  = lane & 3;         // thread-in-group 0..3
    const int rb  = (warp & 3) * 16;  // row block within tile
    const int nc0 = (warp >> 2) * 8;  // nc range [nc0, nc0+8)

    float acc[8][4];
    #pragma unroll
    for (int j = 0; j < 8; ++j)
        acc[j][0] = acc[j][1] = acc[j][2] = acc[j][3] = 0.f;

    // bfrag element index for (kc, nc, lane): (kc*16 + nc)*32 + lane
    const float2* bptr = reinterpret_cast<const float2*>(g_Bfrag) + nc0 * 32 + lane;

    float2 bcur[8];
    #pragma unroll
    for (int j = 0; j < 8; ++j) bcur[j] = bptr[j * 32];

    #pragma unroll
    for (int kc = 0; kc < 16; ++kc) {
        const int k0 = kc * 8;
        // A fragment: load + 2-term split
        const float ar0 = xs[rb + g][k0 + tg];
        const float ar1 = xs[rb + g + 8][k0 + tg];
        const float ar2 = xs[rb + g][k0 + tg + 4];
        const float ar3 = xs[rb + g + 8][k0 + tg + 4];
        const uint32_t h0 = tf32_rna(ar0), h1 = tf32_rna(ar1);
        const uint32_t h2 = tf32_rna(ar2), h3 = tf32_rna(ar3);
        const uint32_t l0 = __float_as_uint(ar0 - __uint_as_float(h0));
        const uint32_t l1 = __float_as_uint(ar1 - __uint_as_float(h1));
        const uint32_t l2 = __float_as_uint(ar2 - __uint_as_float(h2));
        const uint32_t l3 = __float_as_uint(ar3 - __uint_as_float(h3));

        // prefetch next kc's B fragments (LDG issues before the MMA block)
        float2 bnxt[8];
        if (kc < 15) {
            #pragma unroll
            for (int j = 0; j < 8; ++j) bnxt[j] = bptr[(kc + 1) * 512 + j * 32];
        }

        #pragma unroll
        for (int j = 0; j < 8; ++j) {
            const uint32_t bh0 = __float_as_uint(bcur[j].x);
            const uint32_t bh1 = __float_as_uint(bcur[j].y);
            MMA_TF32(acc[j], h0, h1, h2, h3, bh0, bh1);   // hi*hi
            MMA_TF32(acc[j], l0, l1, l2, l3, bh0, bh1);   // lo*hi
        }
        if (kc < 15) {
            #pragma unroll
            for (int j = 0; j < 8; ++j) bcur[j] = bnxt[j];
        }
    }

    // Epilogue: C frag c0/c1 -> (row0+rb+g, col), c2/c3 -> (+8 rows)
    const int r0 = row0 + rb + g;
    const int r1 = r0 + 8;
    const float d0 = (r0 < N_NODES) ? g_dinv[r0] : 0.f;
    const float d1 = (r1 < N_NODES) ? g_dinv[r1] : 0.f;
    #pragma unroll
    for (int j = 0; j < 8; ++j) {
        const int col = (nc0 + j) * 8 + tg * 2;
        if (r0 < N_NODES)
            *reinterpret_cast<float2*>(g_xw + (size_t)r0 * N_FEAT + col) =
                make_float2(acc[j][0] * d0, acc[j][1] * d0);
        if (r1 < N_NODES)
            *reinterpret_cast<float2*>(g_xw + (size_t)r1 * N_FEAT + col) =
                make_float2(acc[j][2] * d1, acc[j][3] * d1);
    }
}

// 5) fused scan stages 2+3
__global__ void k_scan23() {
    __shared__ int sh[128];
    const int t = threadIdx.x;
    int v = 0;
    if (t < 128) { v = (t < NBLK) ? g_bsum[t] : 0; sh[t] = v; }
    __syncthreads();
    #pragma unroll
    for (int off = 1; off < 128; off <<= 1) {
        int add = 0;
        if (t < 128 && t >= off) add = sh[t - off];
        __syncthreads();
        if (t < 128) sh[t] += add;
        __syncthreads();
    }
    if (t < 128) sh[t] -= v;
    __syncthreads();
    const int i = blockIdx.x * blockDim.x + t;
    if (i < N_NODES) {
        int rs = g_rowstart[i] + sh[i >> 10];
        g_rowstart[i] = rs;
        g_cursor[i]   = rs;
    }
}

// 6) bucket-fill
__global__ void k_fill(const int* __restrict__ ei) {
    int e = blockIdx.x * blockDim.x + threadIdx.x;
    if (e < N_EDGES) {
        int c = ei[N_EDGES + e];
        int pos = atomicAdd(&g_cursor[c], 1);
        g_srcs[pos] = ei[e];
    }
}

// ---------------------------------------------------------------------------
// 7) Pull aggregation: one warp per target node. xw pre-scaled by dinv[row].
__global__ __launch_bounds__(256) void k_gather(const float* __restrict__ b,
                                                float* __restrict__ out) {
    const int warp = (blockIdx.x * blockDim.x + threadIdx.x) >> 5;
    const int lane = threadIdx.x & 31;
    if (warp >= N_NODES) return;
    const int c = warp;

    const int base = g_rowstart[c];
    const int cnt  = g_degi[c];

    float4 a0 = make_float4(0.f,0.f,0.f,0.f), a1 = a0, a2 = a0, a3 = a0;
    const float4* xw = reinterpret_cast<const float4*>(g_xw);

    int i = 0;
    for (; i + 4 <= cnt; i += 4) {
        const int s0 = g_srcs[base + i + 0];
        const int s1 = g_srcs[base + i + 1];
        const int s2 = g_srcs[base + i + 2];
        const int s3 = g_srcs[base + i + 3];
        const float4 v0 = xw[(size_t)s0 * 32 + lane];
        const float4 v1 = xw[(size_t)s1 * 32 + lane];
        const float4 v2 = xw[(size_t)s2 * 32 + lane];
        const float4 v3 = xw[(size_t)s3 * 32 + lane];
        a0.x += v0.x; a0.y += v0.y; a0.z += v0.z; a0.w += v0.w;
        a1.x += v1.x; a1.y += v1.y; a1.z += v1.z; a1.w += v1.w;
        a2.x += v2.x; a2.y += v2.y; a2.z += v2.z; a2.w += v2.w;
        a3.x += v3.x; a3.y += v3.y; a3.z += v3.z; a3.w += v3.w;
    }
    for (; i < cnt; ++i) {
        const int s = g_srcs[base + i];
        const float4 v = xw[(size_t)s * 32 + lane];
        a0.x += v.x; a0.y += v.y; a0.z += v.z; a0.w += v.w;
    }

    const float4 self = xw[(size_t)c * 32 + lane];
    float4 acc = make_float4(a0.x + a1.x + a2.x + a3.x + self.x,
                             a0.y + a1.y + a2.y + a3.y + self.y,
                             a0.z + a1.z + a2.z + a3.z + self.z,
                             a0.w + a1.w + a2.w + a3.w + self.w);
    const float nc = g_dinv[c];
    const float4 bv = reinterpret_cast<const float4*>(b)[lane];
    reinterpret_cast<float4*>(out + (size_t)c * N_FEAT)[lane] =
        make_float4(acc.x * nc + bv.x, acc.y * nc + bv.y,
                    acc.z * nc + bv.z, acc.w * nc + bv.w);
}

// ---------------------------------------------------------------------------
extern "C" void kernel_launch(void* const* d_in, const int* in_sizes, int n_in,
                              void* d_out, int out_size) {
    const float* x  = (const float*)d_in[0];
    const int*   ei = (const int*)  d_in[1];
    const float* W  = (const float*)d_in[2];
    const float* b  = (const float*)d_in[3];
    float* out = (float*)d_out;

    k_init_bpack<<<(N_NODES + 255) / 256, 256>>>(W);               // 1
    k_deg_count <<<(N_EDGES + 255) / 256, 256>>>(ei + N_EDGES);    // 2
    k_scan1     <<<NBLK, 256>>>();                                 // 3 (dinv ready)
    k_gemm      <<<(N_NODES + 63) / 64, 256>>>(x);                 // 4 (profiled)
    k_scan23    <<<(N_NODES + 255) / 256, 256>>>();                // 5
    k_fill      <<<(N_EDGES + 255) / 256, 256>>>(ei);              // 6
    k_gather    <<<(N_NODES * 32 + 255) / 256, 256>>>(b, out);     // 7
}